// round 8
// baseline (speedup 1.0000x reference)
#include <cuda_runtime.h>
#include <cuda_fp16.h>

#define B   128
#define H0  224
#define W0  224
#define C1  16
#define HP  56
#define C2  32
#define H2  28
#define W2  28
#define BN_EPS 1e-5f

#define NPIX1 ((double)B * 112.0 * 112.0)
#define NPIX2 ((double)B * H2 * W2)

// ---------------- scratch ----------------
__device__ __half  g_u1[B * HP * HP * C1];     // NHWC pooled conv1 raw, fp16
__device__ __half  g_y2[B * H2 * W2 * C2];     // NHWC conv2 raw, fp16
__device__ double  g_part1[32][C1][2];
__device__ double  g_part2[16][C2][2];
__device__ float   g_logit[B];

// ---------------- f32x2 helpers ----------------
__device__ __forceinline__ unsigned long long pk2(float lo, float hi) {
    unsigned long long r;
    asm("mov.b64 %0, {%1, %2};" : "=l"(r) : "f"(lo), "f"(hi));
    return r;
}
__device__ __forceinline__ void upk2(unsigned long long v, float& lo, float& hi) {
    asm("mov.b64 {%0, %1}, %2;" : "=f"(lo), "=f"(hi) : "l"(v));
}
#define FMA2(acc, a, b) asm("fma.rn.f32x2 %0, %1, %2, %0;" : "+l"(acc) : "l"(a), "l"(b))

__device__ __forceinline__ void u4_to_f8(uint4 u, float* f) {
    float2 a;
    a = __half22float2(*reinterpret_cast<__half2*>(&u.x)); f[0] = a.x; f[1] = a.y;
    a = __half22float2(*reinterpret_cast<__half2*>(&u.y)); f[2] = a.x; f[3] = a.y;
    a = __half22float2(*reinterpret_cast<__half2*>(&u.z)); f[4] = a.x; f[5] = a.y;
    a = __half22float2(*reinterpret_cast<__half2*>(&u.w)); f[6] = a.x; f[7] = a.y;
}

// reduce over the 8 lanes sharing (lane & 3)
__device__ __forceinline__ float qred(float v) {
    v += __shfl_xor_sync(0xffffffffu, v, 16);
    v += __shfl_xor_sync(0xffffffffu, v, 8);
    v += __shfl_xor_sync(0xffffffffu, v, 4);
    return v;
}

// ---------------- kernels ----------------
__global__ void k_nop() {}

__global__ void k_zero() {
    double* p1 = &g_part1[0][0][0];
    double* p2 = &g_part2[0][0][0];
    for (int i = threadIdx.x; i < 32 * C1 * 2; i += blockDim.x) p1[i] = 0.0;
    for (int i = threadIdx.x; i < 16 * C2 * 2; i += blockDim.x) p2[i] = 0.0;
    if (threadIdx.x < B) g_logit[threadIdx.x] = 0.f;
}

// conv1(stride2,pad1; bias cancels in BN) + 2x2 maxpool + BN1 stats.
// Block = 256 thr = 8x8 pooled tile x 4 channel-quarters.
// Tile base col 0 = global col 32*tj-4 so patch rows are 2x aligned LDS.128.
__global__ void __launch_bounds__(256) k_conv1pool(const float* __restrict__ x,
                                                   const float* __restrict__ w) {
    __shared__ __align__(16) float tile[3 * 33 * 36];
    __shared__ __align__(16) unsigned long long ws2[27 * C1];   // [tap][c] (w,w)
    __shared__ float sh_s[C1], sh_q[C1];

    int tid = threadIdx.x;
    int blk = blockIdx.x;                 // n*49 + ti*7 + tj
    int tj  = blk % 7;
    int ti  = (blk / 7) % 7;
    int n   = blk / 49;

    for (int idx = tid; idx < 27 * C1; idx += 256) {
        int c = idx & 15, tap = idx >> 4;
        float wv = w[c * 27 + tap];
        ws2[tap * C1 + c] = pk2(wv, wv);
    }
    if (tid < C1) { sh_s[tid] = 0.f; sh_q[tid] = 0.f; }

    // cooperative tile load: 3ch x 33rows x 9 float4 (cols 32tj-4 .. 32tj+31)
    const int rowg0 = 32 * ti - 1;
    const int colg0 = 32 * tj - 4;
    for (int f = tid; f < 891; f += 256) {
        int quad = f % 9;
        int rt   = f / 9;                 // 0..98
        int ch   = rt / 33;
        int rr   = rt - ch * 33;
        int rg   = rowg0 + rr;
        int cg   = colg0 + 4 * quad;
        float4 v = make_float4(0.f, 0.f, 0.f, 0.f);
        if (rg >= 0 && cg >= 0)
            v = *reinterpret_cast<const float4*>(x + ((n * 3 + ch) * H0 + rg) * W0 + cg);
        *reinterpret_cast<float4*>(&tile[ch * 1188 + rr * 36 + 4 * quad]) = v;
    }
    __syncthreads();

    int quarter = tid & 3;                // 4 channels per thread
    int p       = tid >> 2;               // 0..63 pooled pixel in 8x8 tile
    int pj      = p & 7;
    int pi      = p >> 3;
    int i       = ti * 8 + pi;
    int j       = tj * 8 + pj;

    unsigned long long acc01[4], acc23[4];
#pragma unroll
    for (int c = 0; c < 4; c++) { acc01[c] = 0ull; acc23[c] = 0ull; }

    // patch: global cols 4j-1..4j+3 = smem cols 4pj+3..4pj+7 -> 2 LDS.128/row
    float pr[5][8];
#pragma unroll 1
    for (int ic = 0; ic < 3; ic++) {
        const float* tb = &tile[ic * 1188 + (4 * pi) * 36 + 4 * pj];
#pragma unroll
        for (int r = 0; r < 5; r++) {
            float4 a = *reinterpret_cast<const float4*>(tb + r * 36);
            float4 b = *reinterpret_cast<const float4*>(tb + r * 36 + 4);
            pr[r][0] = a.x; pr[r][1] = a.y; pr[r][2] = a.z; pr[r][3] = a.w;
            pr[r][4] = b.x; pr[r][5] = b.y; pr[r][6] = b.z; pr[r][7] = b.w;
        }
#pragma unroll
        for (int ky = 0; ky < 3; ky++) {
#pragma unroll
            for (int kx = 0; kx < 3; kx++) {
                unsigned long long v01 = pk2(pr[ky][3 + kx],     pr[ky][5 + kx]);
                unsigned long long v23 = pk2(pr[ky + 2][3 + kx], pr[ky + 2][5 + kx]);
                const ulonglong2* wp = reinterpret_cast<const ulonglong2*>(
                    &ws2[(ic * 9 + ky * 3 + kx) * C1 + quarter * 4]);
                ulonglong2 w0 = wp[0], w1 = wp[1];
                FMA2(acc01[0], v01, w0.x); FMA2(acc23[0], v23, w0.x);
                FMA2(acc01[1], v01, w0.y); FMA2(acc23[1], v23, w0.y);
                FMA2(acc01[2], v01, w1.x); FMA2(acc23[2], v23, w1.x);
                FMA2(acc01[3], v01, w1.y); FMA2(acc23[3], v23, w1.y);
            }
        }
    }

    __half hmax[4];
#pragma unroll
    for (int c = 0; c < 4; c++) {
        float a0, a1, a2, a3;
        upk2(acc01[c], a0, a1);
        upk2(acc23[c], a2, a3);
        hmax[c] = __float2half(fmaxf(fmaxf(a0, a1), fmaxf(a2, a3)));
        float s = qred((a0 + a1) + (a2 + a3));
        float q = qred(fmaf(a0, a0, fmaf(a1, a1, fmaf(a2, a2, a3 * a3))));
        if ((tid & 31) < 4) {
            atomicAdd(&sh_s[quarter * 4 + c], s);
            atomicAdd(&sh_q[quarter * 4 + c], q);
        }
    }
    *reinterpret_cast<uint2*>(g_u1 + ((n * HP + i) * HP + j) * C1 + quarter * 4) =
        *reinterpret_cast<uint2*>(&hmax[0]);

    __syncthreads();
    if (tid < C1) {
        int bin = blk & 31;
        atomicAdd(&g_part1[bin][tid][0], (double)sh_s[tid]);
        atomicAdd(&g_part1[bin][tid][1], (double)sh_q[tid]);
    }
}

// conv2(stride2,pad1) + inline BN1+ReLU + BN2 stats; weights via LDS.128 pairs.
__global__ void __launch_bounds__(256) k_conv2(const float* __restrict__ w,
                                               const float* __restrict__ g1,
                                               const float* __restrict__ b1) {
    __shared__ __align__(16) unsigned long long ws2[9 * C1 * 16]; // [tap][ic][pair]
    __shared__ float sc1[C1], sh1[C1];
    __shared__ float s2s[C2], s2q[C2];
    for (int idx = threadIdx.x; idx < 9 * C1 * 16; idx += blockDim.x) {
        int c2p = idx & 15;
        int ic  = (idx >> 4) & 15;
        int q   = idx >> 8;
        ws2[idx] = pk2(w[(2 * c2p) * 144 + ic * 9 + q],
                       w[(2 * c2p + 1) * 144 + ic * 9 + q]);
    }
    if (threadIdx.x < C1) {
        int c = threadIdx.x;
        double s = 0.0, q = 0.0;
#pragma unroll
        for (int bb = 0; bb < 32; bb++) { s += g_part1[bb][c][0]; q += g_part1[bb][c][1]; }
        double mean = s / NPIX1;
        double var  = q / NPIX1 - mean * mean;
        float scale = g1[c] * (1.0f / sqrtf((float)var + BN_EPS));
        sc1[c] = scale;
        sh1[c] = b1[c] - (float)mean * scale;
    }
    if (threadIdx.x < C2) { s2s[threadIdx.x] = 0.f; s2q[threadIdx.x] = 0.f; }
    __syncthreads();

    int t  = blockIdx.x * blockDim.x + threadIdx.x;   // exact: B*28*28
    int wo = t % W2;
    int ho = (t / W2) % H2;
    int n  = t / (W2 * H2);

    unsigned long long acc[16];
#pragma unroll
    for (int c2 = 0; c2 < 16; c2++) acc[c2] = 0ull;

#pragma unroll
    for (int ky = 0; ky < 3; ky++) {
        int row = 2 * ho - 1 + ky;
        bool rok = (row >= 0);
#pragma unroll
        for (int kx = 0; kx < 3; kx++) {
            int col = 2 * wo - 1 + kx;
            if (!rok || col < 0) continue;
            const uint4* p4 = reinterpret_cast<const uint4*>(
                g_u1 + ((n * HP + row) * HP + col) * C1);
            float f[16];
            u4_to_f8(p4[0], f);
            u4_to_f8(p4[1], f + 8);
            const ulonglong2* wq = reinterpret_cast<const ulonglong2*>(
                &ws2[(ky * 3 + kx) * C1 * 16]);
#pragma unroll
            for (int ic = 0; ic < C1; ic++) {
                float h = fmaxf(fmaf(sc1[ic], f[ic], sh1[ic]), 0.f);
                unsigned long long vv = pk2(h, h);
#pragma unroll
                for (int c2 = 0; c2 < 8; c2++) {
                    ulonglong2 ww = wq[ic * 8 + c2];
                    FMA2(acc[2 * c2],     vv, ww.x);
                    FMA2(acc[2 * c2 + 1], vv, ww.y);
                }
            }
        }
    }

    __half hout[C2];
#pragma unroll
    for (int c2 = 0; c2 < 16; c2++) {
        float f0, f1;
        upk2(acc[c2], f0, f1);
        hout[2 * c2]     = __float2half(f0);
        hout[2 * c2 + 1] = __float2half(f1);
        float s0 = f0, q0 = f0 * f0, s1 = f1, q1 = f1 * f1;
#pragma unroll
        for (int o = 16; o > 0; o >>= 1) {
            s0 += __shfl_xor_sync(0xffffffffu, s0, o);
            q0 += __shfl_xor_sync(0xffffffffu, q0, o);
            s1 += __shfl_xor_sync(0xffffffffu, s1, o);
            q1 += __shfl_xor_sync(0xffffffffu, q1, o);
        }
        if ((threadIdx.x & 31) == 0) {
            atomicAdd(&s2s[2 * c2], s0);     atomicAdd(&s2q[2 * c2], q0);
            atomicAdd(&s2s[2 * c2 + 1], s1); atomicAdd(&s2q[2 * c2 + 1], q1);
        }
    }
    uint4* yp = reinterpret_cast<uint4*>(g_y2 + ((n * H2 + ho) * W2 + wo) * C2);
#pragma unroll
    for (int k = 0; k < 4; k++) yp[k] = *reinterpret_cast<uint4*>(&hout[8 * k]);

    __syncthreads();
    if (threadIdx.x < C2) {
        int bin = blockIdx.x & 15;
        atomicAdd(&g_part2[bin][threadIdx.x][0], (double)s2s[threadIdx.x]);
        atomicAdd(&g_part2[bin][threadIdx.x][1], (double)s2q[threadIdx.x]);
    }
}

// BN2+ReLU+avg+fc partials: 2 blocks/sample -> atomic into g_logit
__global__ void __launch_bounds__(256) k_final2(const float* __restrict__ g2,
                                                const float* __restrict__ b2,
                                                const float* __restrict__ fcw) {
    __shared__ float ssc[C2], ssh[C2], sw[C2];
    __shared__ float red[256];
    int tid = threadIdx.x;
    if (tid < C2) {
        double s = 0.0, q = 0.0;
#pragma unroll
        for (int bb = 0; bb < 16; bb++) { s += g_part2[bb][tid][0]; q += g_part2[bb][tid][1]; }
        double mean = s / NPIX2;
        double var  = q / NPIX2 - mean * mean;
        float scale = g2[tid] * (1.0f / sqrtf((float)var + BN_EPS));
        ssc[tid] = scale;
        ssh[tid] = b2[tid] - (float)mean * scale;
        sw[tid]  = fcw[tid];
    }
    __syncthreads();

    int cg = (tid & 3) * 8;
    float rsc[8], rsh[8], rw[8];
#pragma unroll
    for (int k = 0; k < 8; k++) { rsc[k] = ssc[cg + k]; rsh[k] = ssh[cg + k]; rw[k] = sw[cg + k]; }

    int n     = blockIdx.x >> 1;
    int chunk = blockIdx.x & 1;
    const uint4* p = reinterpret_cast<const uint4*>(g_y2 + n * H2 * W2 * C2);
    const int NV = H2 * W2 * C2 / 8;
    int start = chunk * (NV / 2);
    float acc = 0.f;
    for (int i = start + tid; i < start + NV / 2; i += 256) {
        float f[8];
        u4_to_f8(p[i], f);
#pragma unroll
        for (int k = 0; k < 8; k++) {
            float e = fmaxf(fmaf(rsc[k], f[k], rsh[k]), 0.f);
            acc = fmaf(rw[k], e, acc);
        }
    }
    red[tid] = acc;
    __syncthreads();
    for (int o = 128; o > 0; o >>= 1) {
        if (tid < o) red[tid] += red[tid + o];
        __syncthreads();
    }
    if (tid == 0) atomicAdd(&g_logit[n], red[0]);
}

__global__ void k_cos(const float* __restrict__ fcb, float* __restrict__ out) {
    int n = threadIdx.x;
    if (n < B) {
        float logit = g_logit[n] / (float)(H2 * W2) + fcb[0];
        float pr = cosf(logit);
        out[2 * n]     = pr;
        out[2 * n + 1] = 1.f - pr;
    }
}

// ---------------- launcher ----------------
extern "C" void kernel_launch(void* const* d_in, const int* in_sizes, int n_in,
                              void* d_out, int out_size) {
    const float* x    = (const float*)d_in[0];
    const float* c1w  = (const float*)d_in[1];
    const float* bn1g = (const float*)d_in[3];
    const float* bn1b = (const float*)d_in[4];
    const float* c2w  = (const float*)d_in[5];
    const float* bn2g = (const float*)d_in[7];
    const float* bn2b = (const float*)d_in[8];
    const float* fcw  = (const float*)d_in[9];
    const float* fcb  = (const float*)d_in[10];
    float* out = (float*)d_out;

    k_zero<<<1, 256>>>();
    k_conv1pool<<<B * 49, 256>>>(x, c1w);                    // 6272 blocks
    k_nop<<<1, 32>>>();                                      // pad: conv2 -> capture slot
    k_conv2<<<(B * H2 * W2) / 256, 256>>>(c2w, bn1g, bn1b);  // 392 blocks
    k_final2<<<B * 2, 256>>>(bn2g, bn2b, fcw);
    k_cos<<<1, 128>>>(fcb, out);
}

// round 9
// speedup vs baseline: 1.3870x; 1.3870x over previous
#include <cuda_runtime.h>
#include <cuda_fp16.h>

#define B   128
#define H0  224
#define W0  224
#define C1  16
#define HP  56
#define C2  32
#define H2  28
#define W2  28
#define BN_EPS 1e-5f

#define NPIX1 ((double)B * 112.0 * 112.0)
#define NPIX2 ((double)B * H2 * W2)

// ---------------- scratch ----------------
__device__ __half  g_u1[B * HP * HP * C1];     // NHWC pooled conv1 raw, fp16
__device__ __half  g_y2[B * H2 * W2 * C2];     // NHWC conv2 raw, fp16
__device__ double  g_part1[32][C1][2];
__device__ double  g_part2[16][C2][2];
__device__ float   g_logit[B];

// ---------------- f32x2 helpers ----------------
__device__ __forceinline__ unsigned long long pk2(float lo, float hi) {
    unsigned long long r;
    asm("mov.b64 %0, {%1, %2};" : "=l"(r) : "f"(lo), "f"(hi));
    return r;
}
__device__ __forceinline__ void upk2(unsigned long long v, float& lo, float& hi) {
    asm("mov.b64 {%0, %1}, %2;" : "=f"(lo), "=f"(hi) : "l"(v));
}
#define FMA2(acc, a, b) asm("fma.rn.f32x2 %0, %1, %2, %0;" : "+l"(acc) : "l"(a), "l"(b))

__device__ __forceinline__ void u4_to_f8(uint4 u, float* f) {
    float2 a;
    a = __half22float2(*reinterpret_cast<__half2*>(&u.x)); f[0] = a.x; f[1] = a.y;
    a = __half22float2(*reinterpret_cast<__half2*>(&u.y)); f[2] = a.x; f[3] = a.y;
    a = __half22float2(*reinterpret_cast<__half2*>(&u.z)); f[4] = a.x; f[5] = a.y;
    a = __half22float2(*reinterpret_cast<__half2*>(&u.w)); f[6] = a.x; f[7] = a.y;
}

// reduce over the 16 lanes sharing (lane & 1): xor 16,8,4,2 preserves bit0
__device__ __forceinline__ float hred(float v) {
    v += __shfl_xor_sync(0xffffffffu, v, 16);
    v += __shfl_xor_sync(0xffffffffu, v, 8);
    v += __shfl_xor_sync(0xffffffffu, v, 4);
    v += __shfl_xor_sync(0xffffffffu, v, 2);
    return v;
}

// ---------------- kernels ----------------
__global__ void k_nop() {}

__global__ void k_zero() {
    double* p1 = &g_part1[0][0][0];
    double* p2 = &g_part2[0][0][0];
    for (int i = threadIdx.x; i < 32 * C1 * 2; i += blockDim.x) p1[i] = 0.0;
    for (int i = threadIdx.x; i < 16 * C2 * 2; i += blockDim.x) p2[i] = 0.0;
    if (threadIdx.x < B) g_logit[threadIdx.x] = 0.f;
}

// conv1(stride2,pad1; bias cancels in BN) + 2x2 maxpool + BN1 stats.
// Block = 128 thr = 8x8 pooled tile x 2 channel-halves (R6 known-best form).
// Tile base col = global col 32*tj-4 so every patch row is 2 aligned LDS.128.
__global__ void __launch_bounds__(128) k_conv1pool(const float* __restrict__ x,
                                                   const float* __restrict__ w) {
    __shared__ __align__(16) float tile[3 * 33 * 36];
    __shared__ __align__(16) unsigned long long ws2[27 * C1];   // [tap][c] (w,w)
    __shared__ float sh_s[C1], sh_q[C1];

    int tid = threadIdx.x;
    int blk = blockIdx.x;                 // n*49 + ti*7 + tj
    int tj  = blk % 7;
    int ti  = (blk / 7) % 7;
    int n   = blk / 49;

    for (int idx = tid; idx < 27 * C1; idx += 128) {
        int c = idx & 15, tap = idx >> 4;
        float wv = w[c * 27 + tap];
        ws2[tap * C1 + c] = pk2(wv, wv);
    }
    if (tid < C1) { sh_s[tid] = 0.f; sh_q[tid] = 0.f; }

    // cooperative tile load: 3ch x 33rows x 9 float4 (cols 32tj-4 .. 32tj+31)
    const int rowg0 = 32 * ti - 1;
    const int colg0 = 32 * tj - 4;
    for (int f = tid; f < 891; f += 128) {
        int quad = f % 9;
        int rt   = f / 9;                 // 0..98
        int ch   = rt / 33;
        int rr   = rt - ch * 33;
        int rg   = rowg0 + rr;
        int cg   = colg0 + 4 * quad;
        float4 v = make_float4(0.f, 0.f, 0.f, 0.f);
        if (rg >= 0 && cg >= 0)
            v = *reinterpret_cast<const float4*>(x + ((n * 3 + ch) * H0 + rg) * W0 + cg);
        *reinterpret_cast<float4*>(&tile[ch * 1188 + rr * 36 + 4 * quad]) = v;
    }
    __syncthreads();

    int half = tid & 1;                   // 8 channels per thread
    int p    = tid >> 1;                  // 0..63 pooled pixel in 8x8 tile
    int pj   = p & 7;
    int pi   = p >> 3;
    int i    = ti * 8 + pi;
    int j    = tj * 8 + pj;

    unsigned long long acc01[8], acc23[8];
#pragma unroll
    for (int c = 0; c < 8; c++) { acc01[c] = 0ull; acc23[c] = 0ull; }

    // patch: global cols 4j-1..4j+3 = tile cols 4pj+3..4pj+7 -> 2 LDS.128/row
    float pr[5][8];
#pragma unroll 1
    for (int ic = 0; ic < 3; ic++) {
        const float* tb = &tile[ic * 1188 + (4 * pi) * 36 + 4 * pj];
#pragma unroll
        for (int r = 0; r < 5; r++) {
            float4 a = *reinterpret_cast<const float4*>(tb + r * 36);
            float4 b = *reinterpret_cast<const float4*>(tb + r * 36 + 4);
            pr[r][0] = a.x; pr[r][1] = a.y; pr[r][2] = a.z; pr[r][3] = a.w;
            pr[r][4] = b.x; pr[r][5] = b.y; pr[r][6] = b.z; pr[r][7] = b.w;
        }
#pragma unroll
        for (int ky = 0; ky < 3; ky++) {
#pragma unroll
            for (int kx = 0; kx < 3; kx++) {
                unsigned long long v01 = pk2(pr[ky][3 + kx],     pr[ky][5 + kx]);
                unsigned long long v23 = pk2(pr[ky + 2][3 + kx], pr[ky + 2][5 + kx]);
                const ulonglong2* wp = reinterpret_cast<const ulonglong2*>(
                    &ws2[(ic * 9 + ky * 3 + kx) * C1 + half * 8]);
                ulonglong2 w0 = wp[0], w1 = wp[1], w2 = wp[2], w3 = wp[3];
                FMA2(acc01[0], v01, w0.x); FMA2(acc23[0], v23, w0.x);
                FMA2(acc01[1], v01, w0.y); FMA2(acc23[1], v23, w0.y);
                FMA2(acc01[2], v01, w1.x); FMA2(acc23[2], v23, w1.x);
                FMA2(acc01[3], v01, w1.y); FMA2(acc23[3], v23, w1.y);
                FMA2(acc01[4], v01, w2.x); FMA2(acc23[4], v23, w2.x);
                FMA2(acc01[5], v01, w2.y); FMA2(acc23[5], v23, w2.y);
                FMA2(acc01[6], v01, w3.x); FMA2(acc23[6], v23, w3.x);
                FMA2(acc01[7], v01, w3.y); FMA2(acc23[7], v23, w3.y);
            }
        }
    }

    __half hmax[8];
#pragma unroll
    for (int c = 0; c < 8; c++) {
        float a0, a1, a2, a3;
        upk2(acc01[c], a0, a1);
        upk2(acc23[c], a2, a3);
        hmax[c] = __float2half(fmaxf(fmaxf(a0, a1), fmaxf(a2, a3)));
        float s = hred((a0 + a1) + (a2 + a3));
        float q = hred(fmaf(a0, a0, fmaf(a1, a1, fmaf(a2, a2, a3 * a3))));
        if ((tid & 31) < 2) {
            atomicAdd(&sh_s[half * 8 + c], s);
            atomicAdd(&sh_q[half * 8 + c], q);
        }
    }
    *reinterpret_cast<uint4*>(g_u1 + ((n * HP + i) * HP + j) * C1 + half * 8) =
        *reinterpret_cast<uint4*>(&hmax[0]);

    __syncthreads();
    if (tid < C1) {
        int bin = blk & 31;
        atomicAdd(&g_part1[bin][tid][0], (double)sh_s[tid]);
        atomicAdd(&g_part1[bin][tid][1], (double)sh_q[tid]);
    }
}

// conv2(stride2,pad1) + inline BN1+ReLU + BN2 stats.
// Thread = (pixel-PAIR along wo, channel-half): each weight LDS.128 feeds 2 pixels.
__global__ void __launch_bounds__(128) k_conv2(const float* __restrict__ w,
                                               const float* __restrict__ g1,
                                               const float* __restrict__ b1) {
    __shared__ __align__(16) unsigned long long ws2[9 * C1 * 16]; // [tap][ic][pair]
    __shared__ float sc1[C1], sh1[C1];
    __shared__ float s2s[C2], s2q[C2];
    int tid = threadIdx.x;
    for (int idx = tid; idx < 9 * C1 * 16; idx += 128) {
        int c2p = idx & 15;
        int ic  = (idx >> 4) & 15;
        int q   = idx >> 8;
        ws2[idx] = pk2(w[(2 * c2p) * 144 + ic * 9 + q],
                       w[(2 * c2p + 1) * 144 + ic * 9 + q]);
    }
    if (tid < C1) {
        int c = tid;
        double s = 0.0, q = 0.0;
#pragma unroll
        for (int bb = 0; bb < 32; bb++) { s += g_part1[bb][c][0]; q += g_part1[bb][c][1]; }
        double mean = s / NPIX1;
        double var  = q / NPIX1 - mean * mean;
        float scale = g1[c] * (1.0f / sqrtf((float)var + BN_EPS));
        sc1[c] = scale;
        sh1[c] = b1[c] - (float)mean * scale;
    }
    if (tid < C2) { s2s[tid] = 0.f; s2q[tid] = 0.f; }
    __syncthreads();

    int t    = blockIdx.x * 128 + tid;    // exact: B*28*14*2 = 100352
    int half = tid & 1;                   // 16 output channels (8 pairs)
    int r    = t >> 1;
    int q    = r % (W2 / 2);              // pixel-pair: wo = 2q, 2q+1
    int ho   = (r / (W2 / 2)) % H2;
    int n    = r / ((W2 / 2) * H2);

    unsigned long long acc0[8], acc1[8];  // [pair] for pixel0 / pixel1
#pragma unroll
    for (int p = 0; p < 8; p++) { acc0[p] = 0ull; acc1[p] = 0ull; }

#pragma unroll
    for (int ky = 0; ky < 3; ky++) {
        int row = 2 * ho - 1 + ky;
        if (row < 0) continue;            // row <= 55 always
        const __half* rowb = g_u1 + ((n * HP + row) * HP) * C1;
#pragma unroll
        for (int kx = 0; kx < 3; kx++) {
            int col0 = 4 * q - 1 + kx;    // pixel0 tap col; pixel1 = col0+2
            int col1 = col0 + 2;          // always 1..55
            float f0[16], f1[16];
            {
                const uint4* pB = reinterpret_cast<const uint4*>(rowb + col1 * C1);
                u4_to_f8(pB[0], f1);
                u4_to_f8(pB[1], f1 + 8);
            }
            bool v0 = (col0 >= 0);
            if (v0) {
                const uint4* pA = reinterpret_cast<const uint4*>(rowb + col0 * C1);
                u4_to_f8(pA[0], f0);
                u4_to_f8(pA[1], f0 + 8);
            }
            const ulonglong2* wq = reinterpret_cast<const ulonglong2*>(
                &ws2[(ky * 3 + kx) * C1 * 16 + half * 8]);
#pragma unroll
            for (int ic = 0; ic < C1; ic++) {
                float h0 = v0 ? fmaxf(fmaf(sc1[ic], f0[ic], sh1[ic]), 0.f) : 0.f;
                float h1 = fmaxf(fmaf(sc1[ic], f1[ic], sh1[ic]), 0.f);
                unsigned long long vv0 = pk2(h0, h0);
                unsigned long long vv1 = pk2(h1, h1);
                ulonglong2 wa = wq[ic * 8 + 0], wb = wq[ic * 8 + 1],
                           wc = wq[ic * 8 + 2], wd = wq[ic * 8 + 3];
                FMA2(acc0[0], vv0, wa.x); FMA2(acc1[0], vv1, wa.x);
                FMA2(acc0[1], vv0, wa.y); FMA2(acc1[1], vv1, wa.y);
                FMA2(acc0[2], vv0, wb.x); FMA2(acc1[2], vv1, wb.x);
                FMA2(acc0[3], vv0, wb.y); FMA2(acc1[3], vv1, wb.y);
                FMA2(acc0[4], vv0, wc.x); FMA2(acc1[4], vv1, wc.x);
                FMA2(acc0[5], vv0, wc.y); FMA2(acc1[5], vv1, wc.y);
                FMA2(acc0[6], vv0, wd.x); FMA2(acc1[6], vv1, wd.x);
                FMA2(acc0[7], vv0, wd.y); FMA2(acc1[7], vv1, wd.y);
            }
        }
    }

    // stores (16 halves per pixel at channel offset half*16) + BN2 stats
    __half h0out[16], h1out[16];
#pragma unroll
    for (int p = 0; p < 8; p++) {
        float a0, a1, b0, b1;
        upk2(acc0[p], a0, a1);
        upk2(acc1[p], b0, b1);
        h0out[2 * p] = __float2half(a0); h0out[2 * p + 1] = __float2half(a1);
        h1out[2 * p] = __float2half(b0); h1out[2 * p + 1] = __float2half(b1);
        float s0 = hred(a0 + b0), q0 = hred(fmaf(a0, a0, b0 * b0));
        float s1 = hred(a1 + b1), q1 = hred(fmaf(a1, a1, b1 * b1));
        if ((tid & 31) < 2) {
            int c = half * 16 + 2 * p;
            atomicAdd(&s2s[c], s0);     atomicAdd(&s2q[c], q0);
            atomicAdd(&s2s[c + 1], s1); atomicAdd(&s2q[c + 1], q1);
        }
    }
    __half* yb = g_y2 + ((n * H2 + ho) * W2 + 2 * q) * C2 + half * 16;
    reinterpret_cast<uint4*>(yb)[0]      = *reinterpret_cast<uint4*>(&h0out[0]);
    reinterpret_cast<uint4*>(yb)[1]      = *reinterpret_cast<uint4*>(&h0out[8]);
    reinterpret_cast<uint4*>(yb + C2)[0] = *reinterpret_cast<uint4*>(&h1out[0]);
    reinterpret_cast<uint4*>(yb + C2)[1] = *reinterpret_cast<uint4*>(&h1out[8]);

    __syncthreads();
    if (tid < C2) {
        int bin = blockIdx.x & 15;
        atomicAdd(&g_part2[bin][tid][0], (double)s2s[tid]);
        atomicAdd(&g_part2[bin][tid][1], (double)s2q[tid]);
    }
}

// BN2+ReLU+avg+fc partials: 2 blocks/sample -> atomic into g_logit
__global__ void __launch_bounds__(256) k_final2(const float* __restrict__ g2,
                                                const float* __restrict__ b2,
                                                const float* __restrict__ fcw) {
    __shared__ float ssc[C2], ssh[C2], sw[C2];
    __shared__ float red[256];
    int tid = threadIdx.x;
    if (tid < C2) {
        double s = 0.0, q = 0.0;
#pragma unroll
        for (int bb = 0; bb < 16; bb++) { s += g_part2[bb][tid][0]; q += g_part2[bb][tid][1]; }
        double mean = s / NPIX2;
        double var  = q / NPIX2 - mean * mean;
        float scale = g2[tid] * (1.0f / sqrtf((float)var + BN_EPS));
        ssc[tid] = scale;
        ssh[tid] = b2[tid] - (float)mean * scale;
        sw[tid]  = fcw[tid];
    }
    __syncthreads();

    int cg = (tid & 3) * 8;
    float rsc[8], rsh[8], rw[8];
#pragma unroll
    for (int k = 0; k < 8; k++) { rsc[k] = ssc[cg + k]; rsh[k] = ssh[cg + k]; rw[k] = sw[cg + k]; }

    int n     = blockIdx.x >> 1;
    int chunk = blockIdx.x & 1;
    const uint4* p = reinterpret_cast<const uint4*>(g_y2 + n * H2 * W2 * C2);
    const int NV = H2 * W2 * C2 / 8;
    int start = chunk * (NV / 2);
    float acc = 0.f;
    for (int i = start + tid; i < start + NV / 2; i += 256) {
        float f[8];
        u4_to_f8(p[i], f);
#pragma unroll
        for (int k = 0; k < 8; k++) {
            float e = fmaxf(fmaf(rsc[k], f[k], rsh[k]), 0.f);
            acc = fmaf(rw[k], e, acc);
        }
    }
    red[tid] = acc;
    __syncthreads();
    for (int o = 128; o > 0; o >>= 1) {
        if (tid < o) red[tid] += red[tid + o];
        __syncthreads();
    }
    if (tid == 0) atomicAdd(&g_logit[n], red[0]);
}

__global__ void k_cos(const float* __restrict__ fcb, float* __restrict__ out) {
    int n = threadIdx.x;
    if (n < B) {
        float logit = g_logit[n] / (float)(H2 * W2) + fcb[0];
        float pr = cosf(logit);
        out[2 * n]     = pr;
        out[2 * n + 1] = 1.f - pr;
    }
}

// ---------------- launcher ----------------
extern "C" void kernel_launch(void* const* d_in, const int* in_sizes, int n_in,
                              void* d_out, int out_size) {
    const float* x    = (const float*)d_in[0];
    const float* c1w  = (const float*)d_in[1];
    const float* bn1g = (const float*)d_in[3];
    const float* bn1b = (const float*)d_in[4];
    const float* c2w  = (const float*)d_in[5];
    const float* bn2g = (const float*)d_in[7];
    const float* bn2b = (const float*)d_in[8];
    const float* fcw  = (const float*)d_in[9];
    const float* fcb  = (const float*)d_in[10];
    float* out = (float*)d_out;

    k_zero<<<1, 256>>>();
    k_nop<<<1, 32>>>();
    k_nop<<<1, 32>>>();                                      // conv1 -> capture slot 4
    k_conv1pool<<<B * 49, 128>>>(x, c1w);                    // 6272 blocks
    k_conv2<<<(B * H2 * (W2 / 2) * 2) / 128, 128>>>(c2w, bn1g, bn1b); // 784 blocks
    k_final2<<<B * 2, 256>>>(bn2g, bn2b, fcw);
    k_cos<<<1, 128>>>(fcb, out);
}

// round 11
// speedup vs baseline: 1.6273x; 1.1733x over previous
#include <cuda_runtime.h>
#include <cuda_fp16.h>
#include <cstdint>

#define B   128
#define H0  224
#define W0  224
#define C1  16
#define HP  56
#define C2  32
#define H2  28
#define W2  28
#define BN_EPS 1e-5f

#define NPIX1 ((double)B * 112.0 * 112.0)
#define NPIX2 ((double)B * H2 * W2)

// ---------------- scratch ----------------
__device__ __half  g_u1[B * HP * HP * C1];     // NHWC pooled conv1 raw, fp16
__device__ __half  g_y2[B * H2 * W2 * C2];     // NHWC conv2 raw, fp16
__device__ double  g_part1[32][C1][2];
__device__ double  g_part2[16][C2][2];
__device__ float   g_logit[B];

// ---------------- f32x2 helpers ----------------
__device__ __forceinline__ unsigned long long pk2(float lo, float hi) {
    unsigned long long r;
    asm("mov.b64 %0, {%1, %2};" : "=l"(r) : "f"(lo), "f"(hi));
    return r;
}
__device__ __forceinline__ void upk2(unsigned long long v, float& lo, float& hi) {
    asm("mov.b64 {%0, %1}, %2;" : "=f"(lo), "=f"(hi) : "l"(v));
}
#define FMA2(acc, a, b) asm("fma.rn.f32x2 %0, %1, %2, %0;" : "+l"(acc) : "l"(a), "l"(b))

__device__ __forceinline__ void u4_to_f8(uint4 u, float* f) {
    float2 a;
    a = __half22float2(*reinterpret_cast<__half2*>(&u.x)); f[0] = a.x; f[1] = a.y;
    a = __half22float2(*reinterpret_cast<__half2*>(&u.y)); f[2] = a.x; f[3] = a.y;
    a = __half22float2(*reinterpret_cast<__half2*>(&u.z)); f[4] = a.x; f[5] = a.y;
    a = __half22float2(*reinterpret_cast<__half2*>(&u.w)); f[6] = a.x; f[7] = a.y;
}

__device__ __forceinline__ float hred(float v) {
    v += __shfl_xor_sync(0xffffffffu, v, 16);
    v += __shfl_xor_sync(0xffffffffu, v, 8);
    v += __shfl_xor_sync(0xffffffffu, v, 4);
    v += __shfl_xor_sync(0xffffffffu, v, 2);
    return v;
}

// ---------------- kernels ----------------
__global__ void k_nop() {}

__global__ void k_zero() {
    double* p1 = &g_part1[0][0][0];
    double* p2 = &g_part2[0][0][0];
    for (int i = threadIdx.x; i < 32 * C1 * 2; i += blockDim.x) p1[i] = 0.0;
    for (int i = threadIdx.x; i < 16 * C2 * 2; i += blockDim.x) p2[i] = 0.0;
    if (threadIdx.x < B) g_logit[threadIdx.x] = 0.f;
}

// conv1(stride2,pad1; bias cancels in BN) + 2x2 maxpool + BN1 stats via HMMA.
// Implicit GEMM: D[16ch][8pix] = Wa[16][48] x Patch[48][8pix], K = 12taps x 4ic.
// Block 128 thr = 8x8 pooled tile; warp-tile = 2x4 conv pixels (1x2 pooled).
__global__ void __launch_bounds__(128) k_conv1pool(const float* __restrict__ x,
                                                   const float* __restrict__ w) {
    __shared__ __align__(16) __half tile[35 * 36 * 4];   // [row][col][icslot], f16
    __shared__ __align__(16) __half wA[16 * 48];         // [ch][k'] zero-padded
    __shared__ float sh_s[C1], sh_q[C1];

    int tid = threadIdx.x;
    int blk = blockIdx.x;                 // n*49 + bti*7 + btj
    int btj = blk % 7;
    int bti = (blk / 7) % 7;
    int n   = blk / 49;

    // zero the whole tile (incl. pad rows 33-34 and ic slot 3): 630 uint4
    {
        uint4 z = make_uint4(0u, 0u, 0u, 0u);
        uint4* tz = reinterpret_cast<uint4*>(tile);
        for (int i = tid; i < 630; i += 128) tz[i] = z;
    }
    // build zero-padded weight matrix wA[c][k'], k' = tap*4 + ic
    for (int idx = tid; idx < 768; idx += 128) {
        int c = idx / 48, k = idx % 48, tap = k >> 2, ic = k & 3;
        float v = (tap < 9 && ic < 3) ? w[c * 27 + ic * 9 + tap] : 0.f;
        wA[idx] = __float2half(v);
    }
    if (tid < C1) { sh_s[tid] = 0.f; sh_q[tid] = 0.f; }
    __syncthreads();

    // fill tile rows 0..32 (f32 -> f16, ic-interleaved)
    const int rowg0 = 32 * bti - 1;
    const int colg0 = 32 * btj - 4;
    for (int f = tid; f < 891; f += 128) {
        int quad = f % 9;
        int rt   = f / 9;                 // 0..98
        int ch   = rt / 33;
        int rr   = rt - ch * 33;
        int rg   = rowg0 + rr;
        int cg   = colg0 + 4 * quad;
        if (rg >= 0 && cg >= 0) {
            float4 v = *reinterpret_cast<const float4*>(
                x + ((n * 3 + ch) * H0 + rg) * W0 + cg);
            __half* tb = &tile[(rr * 36 + 4 * quad) * 4 + ch];
            tb[0]  = __float2half(v.x);
            tb[4]  = __float2half(v.y);
            tb[8]  = __float2half(v.z);
            tb[12] = __float2half(v.w);
        }
    }
    __syncthreads();

    int lane = tid & 31;
    int warp = tid >> 5;
    int g = lane >> 2;                    // groupID: pixel-n for B, ch rows g/g+8
    int t = lane & 3;

    // per-lane B offsets (in halves): off = ky*144 + kx*4 + ic
    int offA[3], offB[3];
#pragma unroll
    for (int s = 0; s < 3; s++) {
        int ka = 16 * s + 2 * t;
        int tapa = ka >> 2, ica = ka & 3;
        int kya = (tapa < 9) ? tapa / 3 : 3;
        int kxa = (tapa < 9) ? tapa % 3 : (tapa - 9);
        offA[s] = kya * 144 + kxa * 4 + ica;
        int kb = ka + 8;
        int tapb = kb >> 2, icb = kb & 3;
        int kyb = (tapb < 9) ? tapb / 3 : 3;
        int kxb = (tapb < 9) ? tapb % 3 : (tapb - 9);
        offB[s] = kyb * 144 + kxb * 4 + icb;
    }

    // A fragments (constant): a0=A[g][2t,2t+1], a1=A[g+8][..], a2/a3 = k+8
    uint32_t af[3][4];
    {
        const uint32_t* wp = reinterpret_cast<const uint32_t*>(wA);
#pragma unroll
        for (int s = 0; s < 3; s++) {
            int kb = 16 * s + 2 * t;
            af[s][0] = wp[(g * 48 + kb) >> 1];
            af[s][1] = wp[((g + 8) * 48 + kb) >> 1];
            af[s][2] = wp[(g * 48 + kb + 8) >> 1];
            af[s][3] = wp[((g + 8) * 48 + kb + 8) >> 1];
        }
    }

    float s_lo = 0.f, q_lo = 0.f, s_hi = 0.f, q_hi = 0.f;

#pragma unroll 1
    for (int it = 0; it < 8; it++) {
        int tt   = warp + 4 * it;         // 0..31
        int trow = tt >> 2;               // pooled row 0..7
        int tq   = tt & 3;                // pooled col pair 0..3
        int cr   = 2 * trow + (g >> 2);   // this lane's B pixel (conv coords)
        int ccv  = 4 * tq + (g & 3);
        int pixbase = (2 * cr) * 144 + (2 * ccv + 3) * 4;

        float d0 = 0.f, d1 = 0.f, d2 = 0.f, d3 = 0.f;
#pragma unroll
        for (int s = 0; s < 3; s++) {
            uint32_t b0 = *reinterpret_cast<const uint32_t*>(&tile[pixbase + offA[s]]);
            uint32_t b1 = *reinterpret_cast<const uint32_t*>(&tile[pixbase + offB[s]]);
            asm volatile(
                "mma.sync.aligned.m16n8k16.row.col.f32.f16.f16.f32 "
                "{%0,%1,%2,%3}, {%4,%5,%6,%7}, {%8,%9}, {%0,%1,%2,%3};"
                : "+f"(d0), "+f"(d1), "+f"(d2), "+f"(d3)
                : "r"(af[s][0]), "r"(af[s][1]), "r"(af[s][2]), "r"(af[s][3]),
                  "r"(b0), "r"(b1));
        }

        // BN1 stats (pre-pool): lane holds ch g @ pix(2t,2t+1), ch g+8 same pix
        s_lo += d0 + d1;  q_lo = fmaf(d0, d0, fmaf(d1, d1, q_lo));
        s_hi += d2 + d3;  q_hi = fmaf(d2, d2, fmaf(d3, d3, q_hi));

        // maxpool: in-lane horizontal pair, then row0<->row1 via xor 2
        float m0 = fmaxf(d0, d1);
        float m2 = fmaxf(d2, d3);
        m0 = fmaxf(m0, __shfl_xor_sync(0xffffffffu, m0, 2));
        m2 = fmaxf(m2, __shfl_xor_sync(0xffffffffu, m2, 2));
        if (t < 2) {
            int pr = 8 * bti + trow;
            int pc = 8 * btj + 2 * tq + t;
            __half* up = g_u1 + ((n * HP + pr) * HP + pc) * C1;
            up[g]     = __float2half(m0);
            up[g + 8] = __float2half(m2);
        }
    }

    // reduce stats over t (bits 0,1), then to shared, then to global bins
    s_lo += __shfl_xor_sync(0xffffffffu, s_lo, 1);
    s_lo += __shfl_xor_sync(0xffffffffu, s_lo, 2);
    q_lo += __shfl_xor_sync(0xffffffffu, q_lo, 1);
    q_lo += __shfl_xor_sync(0xffffffffu, q_lo, 2);
    s_hi += __shfl_xor_sync(0xffffffffu, s_hi, 1);
    s_hi += __shfl_xor_sync(0xffffffffu, s_hi, 2);
    q_hi += __shfl_xor_sync(0xffffffffu, q_hi, 1);
    q_hi += __shfl_xor_sync(0xffffffffu, q_hi, 2);
    if (t == 0) {
        atomicAdd(&sh_s[g], s_lo);     atomicAdd(&sh_q[g], q_lo);
        atomicAdd(&sh_s[g + 8], s_hi); atomicAdd(&sh_q[g + 8], q_hi);
    }
    __syncthreads();
    if (tid < C1) {
        int bin = blk & 31;
        atomicAdd(&g_part1[bin][tid][0], (double)sh_s[tid]);
        atomicAdd(&g_part1[bin][tid][1], (double)sh_q[tid]);
    }
}

// conv2(stride2,pad1) + inline BN1+ReLU + BN2 stats (R9 proven form).
__global__ void __launch_bounds__(128) k_conv2(const float* __restrict__ w,
                                               const float* __restrict__ g1,
                                               const float* __restrict__ b1) {
    __shared__ __align__(16) unsigned long long ws2[9 * C1 * 16];
    __shared__ float sc1[C1], sh1[C1];
    __shared__ float s2s[C2], s2q[C2];
    int tid = threadIdx.x;
    for (int idx = tid; idx < 9 * C1 * 16; idx += 128) {
        int c2p = idx & 15;
        int ic  = (idx >> 4) & 15;
        int q   = idx >> 8;
        ws2[idx] = pk2(w[(2 * c2p) * 144 + ic * 9 + q],
                       w[(2 * c2p + 1) * 144 + ic * 9 + q]);
    }
    if (tid < C1) {
        int c = tid;
        double s = 0.0, q = 0.0;
#pragma unroll
        for (int bb = 0; bb < 32; bb++) { s += g_part1[bb][c][0]; q += g_part1[bb][c][1]; }
        double mean = s / NPIX1;
        double var  = q / NPIX1 - mean * mean;
        float scale = g1[c] * (1.0f / sqrtf((float)var + BN_EPS));
        sc1[c] = scale;
        sh1[c] = b1[c] - (float)mean * scale;
    }
    if (tid < C2) { s2s[tid] = 0.f; s2q[tid] = 0.f; }
    __syncthreads();

    int t    = blockIdx.x * 128 + tid;
    int half = tid & 1;
    int r    = t >> 1;
    int q    = r % (W2 / 2);
    int ho   = (r / (W2 / 2)) % H2;
    int n    = r / ((W2 / 2) * H2);

    unsigned long long acc0[8], acc1[8];
#pragma unroll
    for (int p = 0; p < 8; p++) { acc0[p] = 0ull; acc1[p] = 0ull; }

#pragma unroll
    for (int ky = 0; ky < 3; ky++) {
        int row = 2 * ho - 1 + ky;
        if (row < 0) continue;
        const __half* rowb = g_u1 + ((n * HP + row) * HP) * C1;
#pragma unroll
        for (int kx = 0; kx < 3; kx++) {
            int col0 = 4 * q - 1 + kx;
            int col1 = col0 + 2;
            float f0[16], f1[16];
            {
                const uint4* pB = reinterpret_cast<const uint4*>(rowb + col1 * C1);
                u4_to_f8(pB[0], f1);
                u4_to_f8(pB[1], f1 + 8);
            }
            bool v0 = (col0 >= 0);
            if (v0) {
                const uint4* pA = reinterpret_cast<const uint4*>(rowb + col0 * C1);
                u4_to_f8(pA[0], f0);
                u4_to_f8(pA[1], f0 + 8);
            }
            const ulonglong2* wq = reinterpret_cast<const ulonglong2*>(
                &ws2[(ky * 3 + kx) * C1 * 16 + half * 8]);
#pragma unroll
            for (int ic = 0; ic < C1; ic++) {
                float h0 = v0 ? fmaxf(fmaf(sc1[ic], f0[ic], sh1[ic]), 0.f) : 0.f;
                float h1 = fmaxf(fmaf(sc1[ic], f1[ic], sh1[ic]), 0.f);
                unsigned long long vv0 = pk2(h0, h0);
                unsigned long long vv1 = pk2(h1, h1);
                ulonglong2 wa = wq[ic * 8 + 0], wb = wq[ic * 8 + 1],
                           wc = wq[ic * 8 + 2], wd = wq[ic * 8 + 3];
                FMA2(acc0[0], vv0, wa.x); FMA2(acc1[0], vv1, wa.x);
                FMA2(acc0[1], vv0, wa.y); FMA2(acc1[1], vv1, wa.y);
                FMA2(acc0[2], vv0, wb.x); FMA2(acc1[2], vv1, wb.x);
                FMA2(acc0[3], vv0, wb.y); FMA2(acc1[3], vv1, wb.y);
                FMA2(acc0[4], vv0, wc.x); FMA2(acc1[4], vv1, wc.x);
                FMA2(acc0[5], vv0, wc.y); FMA2(acc1[5], vv1, wc.y);
                FMA2(acc0[6], vv0, wd.x); FMA2(acc1[6], vv1, wd.x);
                FMA2(acc0[7], vv0, wd.y); FMA2(acc1[7], vv1, wd.y);
            }
        }
    }

    __half h0out[16], h1out[16];
#pragma unroll
    for (int p = 0; p < 8; p++) {
        float a0, a1, b0, b1;
        upk2(acc0[p], a0, a1);
        upk2(acc1[p], b0, b1);
        h0out[2 * p] = __float2half(a0); h0out[2 * p + 1] = __float2half(a1);
        h1out[2 * p] = __float2half(b0); h1out[2 * p + 1] = __float2half(b1);
        float s0 = hred(a0 + b0), q0 = hred(fmaf(a0, a0, b0 * b0));
        float s1 = hred(a1 + b1), q1 = hred(fmaf(a1, a1, b1 * b1));
        if ((tid & 31) < 2) {
            int c = half * 16 + 2 * p;
            atomicAdd(&s2s[c], s0);     atomicAdd(&s2q[c], q0);
            atomicAdd(&s2s[c + 1], s1); atomicAdd(&s2q[c + 1], q1);
        }
    }
    __half* yb = g_y2 + ((n * H2 + ho) * W2 + 2 * q) * C2 + half * 16;
    reinterpret_cast<uint4*>(yb)[0]      = *reinterpret_cast<uint4*>(&h0out[0]);
    reinterpret_cast<uint4*>(yb)[1]      = *reinterpret_cast<uint4*>(&h0out[8]);
    reinterpret_cast<uint4*>(yb + C2)[0] = *reinterpret_cast<uint4*>(&h1out[0]);
    reinterpret_cast<uint4*>(yb + C2)[1] = *reinterpret_cast<uint4*>(&h1out[8]);

    __syncthreads();
    if (tid < C2) {
        int bin = blockIdx.x & 15;
        atomicAdd(&g_part2[bin][tid][0], (double)s2s[tid]);
        atomicAdd(&g_part2[bin][tid][1], (double)s2q[tid]);
    }
}

// BN2+ReLU+avg+fc partials: 2 blocks/sample -> atomic into g_logit
__global__ void __launch_bounds__(256) k_final2(const float* __restrict__ g2,
                                                const float* __restrict__ b2,
                                                const float* __restrict__ fcw) {
    __shared__ float ssc[C2], ssh[C2], sw[C2];
    __shared__ float red[256];
    int tid = threadIdx.x;
    if (tid < C2) {
        double s = 0.0, q = 0.0;
#pragma unroll
        for (int bb = 0; bb < 16; bb++) { s += g_part2[bb][tid][0]; q += g_part2[bb][tid][1]; }
        double mean = s / NPIX2;
        double var  = q / NPIX2 - mean * mean;
        float scale = g2[tid] * (1.0f / sqrtf((float)var + BN_EPS));
        ssc[tid] = scale;
        ssh[tid] = b2[tid] - (float)mean * scale;
        sw[tid]  = fcw[tid];
    }
    __syncthreads();

    int cg = (tid & 3) * 8;
    float rsc[8], rsh[8], rw[8];
#pragma unroll
    for (int k = 0; k < 8; k++) { rsc[k] = ssc[cg + k]; rsh[k] = ssh[cg + k]; rw[k] = sw[cg + k]; }

    int n     = blockIdx.x >> 1;
    int chunk = blockIdx.x & 1;
    const uint4* p = reinterpret_cast<const uint4*>(g_y2 + n * H2 * W2 * C2);
    const int NV = H2 * W2 * C2 / 8;
    int start = chunk * (NV / 2);
    float acc = 0.f;
    for (int i = start + tid; i < start + NV / 2; i += 256) {
        float f[8];
        u4_to_f8(p[i], f);
#pragma unroll
        for (int k = 0; k < 8; k++) {
            float e = fmaxf(fmaf(rsc[k], f[k], rsh[k]), 0.f);
            acc = fmaf(rw[k], e, acc);
        }
    }
    red[tid] = acc;
    __syncthreads();
    for (int o = 128; o > 0; o >>= 1) {
        if (tid < o) red[tid] += red[tid + o];
        __syncthreads();
    }
    if (tid == 0) atomicAdd(&g_logit[n], red[0]);
}

__global__ void k_cos(const float* __restrict__ fcb, float* __restrict__ out) {
    int n = threadIdx.x;
    if (n < B) {
        float logit = g_logit[n] / (float)(H2 * W2) + fcb[0];
        float pr = cosf(logit);
        out[2 * n]     = pr;
        out[2 * n + 1] = 1.f - pr;
    }
}

// ---------------- launcher ----------------
extern "C" void kernel_launch(void* const* d_in, const int* in_sizes, int n_in,
                              void* d_out, int out_size) {
    const float* x    = (const float*)d_in[0];
    const float* c1w  = (const float*)d_in[1];
    const float* bn1g = (const float*)d_in[3];
    const float* bn1b = (const float*)d_in[4];
    const float* c2w  = (const float*)d_in[5];
    const float* bn2g = (const float*)d_in[7];
    const float* bn2b = (const float*)d_in[8];
    const float* fcw  = (const float*)d_in[9];
    const float* fcb  = (const float*)d_in[10];
    float* out = (float*)d_out;

    k_zero<<<1, 256>>>();
    k_nop<<<1, 32>>>();
    k_nop<<<1, 32>>>();                                      // conv1 -> capture slot 4
    k_conv1pool<<<B * 49, 128>>>(x, c1w);                    // 6272 blocks
    k_conv2<<<(B * H2 * (W2 / 2) * 2) / 128, 128>>>(c2w, bn1g, bn1b); // 784 blocks
    k_final2<<<B * 2, 256>>>(bn2g, bn2b, fcw);
    k_cos<<<1, 128>>>(fcb, out);
}

// round 12
// speedup vs baseline: 1.9176x; 1.1783x over previous
#include <cuda_runtime.h>
#include <cuda_fp16.h>
#include <cstdint>

#define B   128
#define H0  224
#define W0  224
#define C1  16
#define HP  56
#define C2  32
#define H2  28
#define W2  28
#define BN_EPS 1e-5f

#define NPIX1 ((double)B * 112.0 * 112.0)
#define NPIX2 ((double)B * H2 * W2)

// ---------------- scratch ----------------
__device__ __half  g_u1[B * HP * HP * C1];     // NHWC pooled conv1 raw, fp16
__device__ __half  g_y2[B * H2 * W2 * C2];     // NHWC conv2 raw, fp16
__device__ double  g_part1[32][C1][2];
__device__ double  g_part2[16][C2][2];
__device__ float   g_logit[B];

// ---------------- f32x2 helpers ----------------
__device__ __forceinline__ unsigned long long pk2(float lo, float hi) {
    unsigned long long r;
    asm("mov.b64 %0, {%1, %2};" : "=l"(r) : "f"(lo), "f"(hi));
    return r;
}
__device__ __forceinline__ void upk2(unsigned long long v, float& lo, float& hi) {
    asm("mov.b64 {%0, %1}, %2;" : "=f"(lo), "=f"(hi) : "l"(v));
}
#define FMA2(acc, a, b) asm("fma.rn.f32x2 %0, %1, %2, %0;" : "+l"(acc) : "l"(a), "l"(b))

__device__ __forceinline__ void u4_to_f8(uint4 u, float* f) {
    float2 a;
    a = __half22float2(*reinterpret_cast<__half2*>(&u.x)); f[0] = a.x; f[1] = a.y;
    a = __half22float2(*reinterpret_cast<__half2*>(&u.y)); f[2] = a.x; f[3] = a.y;
    a = __half22float2(*reinterpret_cast<__half2*>(&u.z)); f[4] = a.x; f[5] = a.y;
    a = __half22float2(*reinterpret_cast<__half2*>(&u.w)); f[6] = a.x; f[7] = a.y;
}

__device__ __forceinline__ float hred(float v) {
    v += __shfl_xor_sync(0xffffffffu, v, 16);
    v += __shfl_xor_sync(0xffffffffu, v, 8);
    v += __shfl_xor_sync(0xffffffffu, v, 4);
    v += __shfl_xor_sync(0xffffffffu, v, 2);
    return v;
}

// ---------------- kernels ----------------
__global__ void k_nop() {}

__global__ void k_zero() {
    double* p1 = &g_part1[0][0][0];
    double* p2 = &g_part2[0][0][0];
    for (int i = threadIdx.x; i < 32 * C1 * 2; i += blockDim.x) p1[i] = 0.0;
    for (int i = threadIdx.x; i < 16 * C2 * 2; i += blockDim.x) p2[i] = 0.0;
    if (threadIdx.x < B) g_logit[threadIdx.x] = 0.f;
}

// conv1(stride2,pad1; bias cancels in BN) + 2x2 maxpool + BN1 stats via HMMA.
// GEMM K-order: k' = ic*16 + ky*4 + slot; slot0 & ky3 are zero-weight pads so
// fragment k-pairs are ALIGNED adjacent columns of a PLANAR [ic][row][col] tile.
// Block 128 thr = 8x8 pooled tile; warp-tile = 16ch x 8 conv pixels.
__global__ void __launch_bounds__(128) k_conv1pool(const float* __restrict__ x,
                                                   const float* __restrict__ w) {
    __shared__ __align__(16) __half tile[3 * 34 * 36];   // planar [ic][row][col]
    __shared__ __align__(16) __half wA[16 * 48];         // [ch][k'] permuted/padded
    __shared__ float sh_s[C1], sh_q[C1];

    int tid = threadIdx.x;
    int blk = blockIdx.x;                 // n*49 + bti*7 + btj
    int btj = blk % 7;
    int bti = (blk / 7) % 7;
    int n   = blk / 49;

    // zero tile: 3*34*36 halves = 459 uint4
    {
        uint4 z = make_uint4(0u, 0u, 0u, 0u);
        uint4* tz = reinterpret_cast<uint4*>(tile);
        for (int i = tid; i < 459; i += 128) tz[i] = z;
    }
    // weights: c = tid&15, 6 consecutive k' each (all shift/mask math)
    {
        int c  = tid & 15;
        int k0 = (tid >> 4) * 6;
#pragma unroll
        for (int u = 0; u < 6; u++) {
            int k  = k0 + u;              // 0..47
            int ic = k >> 4, r = k & 15, ky = r >> 2, slot = r & 3;
            float v = (slot > 0 && ky < 3) ? w[c * 27 + ic * 9 + ky * 3 + (slot - 1)] : 0.f;
            wA[c * 48 + k] = __float2half(v);
        }
    }
    if (tid < C1) { sh_s[tid] = 0.f; sh_q[tid] = 0.f; }
    __syncthreads();

    // fill tile rows 0..32 planar fp16: one STS.64 per float4 (contiguous)
    const int rowg0 = 32 * bti - 1;
    const int colg0 = 32 * btj - 4;
    {
        int quad = tid % 9;               // 0..8
        int rt   = tid / 9;               // 0..14
        for (int f = tid; f < 891; f += 128) {
            int ch = (rt >= 66) ? 2 : (rt >= 33 ? 1 : 0);
            int rr = rt - ch * 33;
            int rg = rowg0 + rr;
            int cg = colg0 + 4 * quad;
            if (rg >= 0 && cg >= 0) {
                float4 v = *reinterpret_cast<const float4*>(
                    x + ((n * 3 + ch) * H0 + rg) * W0 + cg);
                __half2 h01 = __floats2half2_rn(v.x, v.y);
                __half2 h23 = __floats2half2_rn(v.z, v.w);
                uint2 st;
                st.x = *reinterpret_cast<unsigned int*>(&h01);
                st.y = *reinterpret_cast<unsigned int*>(&h23);
                *reinterpret_cast<uint2*>(&tile[ch * 1224 + rr * 36 + 4 * quad]) = st;
            }
            quad += 2; rt += 14;
            if (quad >= 9) { quad -= 9; rt++; }
        }
    }
    __syncthreads();

    int lane = tid & 31;
    int warp = tid >> 5;
    int g = lane >> 2;                    // B pixel index / A ch rows g,g+8
    int t = lane & 3;
    int g2 = g >> 2, g3 = g & 3;

    // lane-constant B offsets (halves): row ky=(t>>1) [+2 for hi], col 2(t&1)
    int coff = (t >> 1) * 36 + 2 * (t & 1) + 2;   // +2 = slot0 pad col start
    int gconst = 72 * g2 + 2 * g3;

    // A fragments (permuted k'): af[s] covers k' 16s..16s+15
    uint32_t af[3][4];
    {
        const uint32_t* wp = reinterpret_cast<const uint32_t*>(wA);
#pragma unroll
        for (int s = 0; s < 3; s++) {
            int kb = 16 * s + 2 * t;
            af[s][0] = wp[(g * 48 + kb) >> 1];
            af[s][1] = wp[((g + 8) * 48 + kb) >> 1];
            af[s][2] = wp[(g * 48 + kb + 8) >> 1];
            af[s][3] = wp[((g + 8) * 48 + kb + 8) >> 1];
        }
    }

    float s_lo = 0.f, q_lo = 0.f, s_hi = 0.f, q_hi = 0.f;

#pragma unroll 1
    for (int it = 0; it < 8; it++) {
        int tt   = warp + 4 * it;         // 0..31
        int trow = tt >> 2;               // pooled row 0..7
        int tq   = tt & 3;                // pooled col pair 0..3
        int base = 144 * trow + 8 * tq + gconst + coff;  // half-offset, 4B aligned

        float d0 = 0.f, d1 = 0.f, d2 = 0.f, d3 = 0.f;
#pragma unroll
        for (int s = 0; s < 3; s++) {
            uint32_t b0 = *reinterpret_cast<const uint32_t*>(&tile[s * 1224 + base]);
            uint32_t b1 = *reinterpret_cast<const uint32_t*>(&tile[s * 1224 + base + 72]);
            asm volatile(
                "mma.sync.aligned.m16n8k16.row.col.f32.f16.f16.f32 "
                "{%0,%1,%2,%3}, {%4,%5,%6,%7}, {%8,%9}, {%0,%1,%2,%3};"
                : "+f"(d0), "+f"(d1), "+f"(d2), "+f"(d3)
                : "r"(af[s][0]), "r"(af[s][1]), "r"(af[s][2]), "r"(af[s][3]),
                  "r"(b0), "r"(b1));
        }

        // BN1 stats (pre-pool): lane holds ch g @ pix(2t,2t+1), ch g+8 same pix
        s_lo += d0 + d1;  q_lo = fmaf(d0, d0, fmaf(d1, d1, q_lo));
        s_hi += d2 + d3;  q_hi = fmaf(d2, d2, fmaf(d3, d3, q_hi));

        // maxpool: in-lane horizontal pair, then row0<->row1 via xor 2
        float m0 = fmaxf(d0, d1);
        float m2 = fmaxf(d2, d3);
        m0 = fmaxf(m0, __shfl_xor_sync(0xffffffffu, m0, 2));
        m2 = fmaxf(m2, __shfl_xor_sync(0xffffffffu, m2, 2));
        if (t < 2) {
            int pr = 8 * bti + trow;
            int pc = 8 * btj + 2 * tq + t;
            __half* up = g_u1 + ((n * HP + pr) * HP + pc) * C1;
            up[g]     = __float2half(m0);
            up[g + 8] = __float2half(m2);
        }
    }

    // reduce stats over t (bits 0,1), then shared, then global bins
    s_lo += __shfl_xor_sync(0xffffffffu, s_lo, 1);
    s_lo += __shfl_xor_sync(0xffffffffu, s_lo, 2);
    q_lo += __shfl_xor_sync(0xffffffffu, q_lo, 1);
    q_lo += __shfl_xor_sync(0xffffffffu, q_lo, 2);
    s_hi += __shfl_xor_sync(0xffffffffu, s_hi, 1);
    s_hi += __shfl_xor_sync(0xffffffffu, s_hi, 2);
    q_hi += __shfl_xor_sync(0xffffffffu, q_hi, 1);
    q_hi += __shfl_xor_sync(0xffffffffu, q_hi, 2);
    if (t == 0) {
        atomicAdd(&sh_s[g], s_lo);     atomicAdd(&sh_q[g], q_lo);
        atomicAdd(&sh_s[g + 8], s_hi); atomicAdd(&sh_q[g + 8], q_hi);
    }
    __syncthreads();
    if (tid < C1) {
        int bin = blk & 31;
        atomicAdd(&g_part1[bin][tid][0], (double)sh_s[tid]);
        atomicAdd(&g_part1[bin][tid][1], (double)sh_q[tid]);
    }
}

// conv2(stride2,pad1) + inline BN1+ReLU + BN2 stats (R9 proven form).
__global__ void __launch_bounds__(128) k_conv2(const float* __restrict__ w,
                                               const float* __restrict__ g1,
                                               const float* __restrict__ b1) {
    __shared__ __align__(16) unsigned long long ws2[9 * C1 * 16];
    __shared__ float sc1[C1], sh1[C1];
    __shared__ float s2s[C2], s2q[C2];
    int tid = threadIdx.x;
    for (int idx = tid; idx < 9 * C1 * 16; idx += 128) {
        int c2p = idx & 15;
        int ic  = (idx >> 4) & 15;
        int q   = idx >> 8;
        ws2[idx] = pk2(w[(2 * c2p) * 144 + ic * 9 + q],
                       w[(2 * c2p + 1) * 144 + ic * 9 + q]);
    }
    if (tid < C1) {
        int c = tid;
        double s = 0.0, q = 0.0;
#pragma unroll
        for (int bb = 0; bb < 32; bb++) { s += g_part1[bb][c][0]; q += g_part1[bb][c][1]; }
        double mean = s / NPIX1;
        double var  = q / NPIX1 - mean * mean;
        float scale = g1[c] * (1.0f / sqrtf((float)var + BN_EPS));
        sc1[c] = scale;
        sh1[c] = b1[c] - (float)mean * scale;
    }
    if (tid < C2) { s2s[tid] = 0.f; s2q[tid] = 0.f; }
    __syncthreads();

    int t    = blockIdx.x * 128 + tid;
    int half = tid & 1;
    int r    = t >> 1;
    int q    = r % (W2 / 2);
    int ho   = (r / (W2 / 2)) % H2;
    int n    = r / ((W2 / 2) * H2);

    unsigned long long acc0[8], acc1[8];
#pragma unroll
    for (int p = 0; p < 8; p++) { acc0[p] = 0ull; acc1[p] = 0ull; }

#pragma unroll
    for (int ky = 0; ky < 3; ky++) {
        int row = 2 * ho - 1 + ky;
        if (row < 0) continue;
        const __half* rowb = g_u1 + ((n * HP + row) * HP) * C1;
#pragma unroll
        for (int kx = 0; kx < 3; kx++) {
            int col0 = 4 * q - 1 + kx;
            int col1 = col0 + 2;
            float f0[16], f1[16];
            {
                const uint4* pB = reinterpret_cast<const uint4*>(rowb + col1 * C1);
                u4_to_f8(pB[0], f1);
                u4_to_f8(pB[1], f1 + 8);
            }
            bool v0 = (col0 >= 0);
            if (v0) {
                const uint4* pA = reinterpret_cast<const uint4*>(rowb + col0 * C1);
                u4_to_f8(pA[0], f0);
                u4_to_f8(pA[1], f0 + 8);
            }
            const ulonglong2* wq = reinterpret_cast<const ulonglong2*>(
                &ws2[(ky * 3 + kx) * C1 * 16 + half * 8]);
#pragma unroll
            for (int ic = 0; ic < C1; ic++) {
                float h0 = v0 ? fmaxf(fmaf(sc1[ic], f0[ic], sh1[ic]), 0.f) : 0.f;
                float h1 = fmaxf(fmaf(sc1[ic], f1[ic], sh1[ic]), 0.f);
                unsigned long long vv0 = pk2(h0, h0);
                unsigned long long vv1 = pk2(h1, h1);
                ulonglong2 wa = wq[ic * 8 + 0], wb = wq[ic * 8 + 1],
                           wc = wq[ic * 8 + 2], wd = wq[ic * 8 + 3];
                FMA2(acc0[0], vv0, wa.x); FMA2(acc1[0], vv1, wa.x);
                FMA2(acc0[1], vv0, wa.y); FMA2(acc1[1], vv1, wa.y);
                FMA2(acc0[2], vv0, wb.x); FMA2(acc1[2], vv1, wb.x);
                FMA2(acc0[3], vv0, wb.y); FMA2(acc1[3], vv1, wb.y);
                FMA2(acc0[4], vv0, wc.x); FMA2(acc1[4], vv1, wc.x);
                FMA2(acc0[5], vv0, wc.y); FMA2(acc1[5], vv1, wc.y);
                FMA2(acc0[6], vv0, wd.x); FMA2(acc1[6], vv1, wd.x);
                FMA2(acc0[7], vv0, wd.y); FMA2(acc1[7], vv1, wd.y);
            }
        }
    }

    __half h0out[16], h1out[16];
#pragma unroll
    for (int p = 0; p < 8; p++) {
        float a0, a1, b0, b1;
        upk2(acc0[p], a0, a1);
        upk2(acc1[p], b0, b1);
        h0out[2 * p] = __float2half(a0); h0out[2 * p + 1] = __float2half(a1);
        h1out[2 * p] = __float2half(b0); h1out[2 * p + 1] = __float2half(b1);
        float s0 = hred(a0 + b0), q0 = hred(fmaf(a0, a0, b0 * b0));
        float s1 = hred(a1 + b1), q1 = hred(fmaf(a1, a1, b1 * b1));
        if ((tid & 31) < 2) {
            int c = half * 16 + 2 * p;
            atomicAdd(&s2s[c], s0);     atomicAdd(&s2q[c], q0);
            atomicAdd(&s2s[c + 1], s1); atomicAdd(&s2q[c + 1], q1);
        }
    }
    __half* yb = g_y2 + ((n * H2 + ho) * W2 + 2 * q) * C2 + half * 16;
    reinterpret_cast<uint4*>(yb)[0]      = *reinterpret_cast<uint4*>(&h0out[0]);
    reinterpret_cast<uint4*>(yb)[1]      = *reinterpret_cast<uint4*>(&h0out[8]);
    reinterpret_cast<uint4*>(yb + C2)[0] = *reinterpret_cast<uint4*>(&h1out[0]);
    reinterpret_cast<uint4*>(yb + C2)[1] = *reinterpret_cast<uint4*>(&h1out[8]);

    __syncthreads();
    if (tid < C2) {
        int bin = blockIdx.x & 15;
        atomicAdd(&g_part2[bin][tid][0], (double)s2s[tid]);
        atomicAdd(&g_part2[bin][tid][1], (double)s2q[tid]);
    }
}

// BN2+ReLU+avg+fc partials: 2 blocks/sample -> atomic into g_logit
__global__ void __launch_bounds__(256) k_final2(const float* __restrict__ g2,
                                                const float* __restrict__ b2,
                                                const float* __restrict__ fcw) {
    __shared__ float ssc[C2], ssh[C2], sw[C2];
    __shared__ float red[256];
    int tid = threadIdx.x;
    if (tid < C2) {
        double s = 0.0, q = 0.0;
#pragma unroll
        for (int bb = 0; bb < 16; bb++) { s += g_part2[bb][tid][0]; q += g_part2[bb][tid][1]; }
        double mean = s / NPIX2;
        double var  = q / NPIX2 - mean * mean;
        float scale = g2[tid] * (1.0f / sqrtf((float)var + BN_EPS));
        ssc[tid] = scale;
        ssh[tid] = b2[tid] - (float)mean * scale;
        sw[tid]  = fcw[tid];
    }
    __syncthreads();

    int cg = (tid & 3) * 8;
    float rsc[8], rsh[8], rw[8];
#pragma unroll
    for (int k = 0; k < 8; k++) { rsc[k] = ssc[cg + k]; rsh[k] = ssh[cg + k]; rw[k] = sw[cg + k]; }

    int n     = blockIdx.x >> 1;
    int chunk = blockIdx.x & 1;
    const uint4* p = reinterpret_cast<const uint4*>(g_y2 + n * H2 * W2 * C2);
    const int NV = H2 * W2 * C2 / 8;
    int start = chunk * (NV / 2);
    float acc = 0.f;
    for (int i = start + tid; i < start + NV / 2; i += 256) {
        float f[8];
        u4_to_f8(p[i], f);
#pragma unroll
        for (int k = 0; k < 8; k++) {
            float e = fmaxf(fmaf(rsc[k], f[k], rsh[k]), 0.f);
            acc = fmaf(rw[k], e, acc);
        }
    }
    red[tid] = acc;
    __syncthreads();
    for (int o = 128; o > 0; o >>= 1) {
        if (tid < o) red[tid] += red[tid + o];
        __syncthreads();
    }
    if (tid == 0) atomicAdd(&g_logit[n], red[0]);
}

__global__ void k_cos(const float* __restrict__ fcb, float* __restrict__ out) {
    int n = threadIdx.x;
    if (n < B) {
        float logit = g_logit[n] / (float)(H2 * W2) + fcb[0];
        float pr = cosf(logit);
        out[2 * n]     = pr;
        out[2 * n + 1] = 1.f - pr;
    }
}

// ---------------- launcher ----------------
extern "C" void kernel_launch(void* const* d_in, const int* in_sizes, int n_in,
                              void* d_out, int out_size) {
    const float* x    = (const float*)d_in[0];
    const float* c1w  = (const float*)d_in[1];
    const float* bn1g = (const float*)d_in[3];
    const float* bn1b = (const float*)d_in[4];
    const float* c2w  = (const float*)d_in[5];
    const float* bn2g = (const float*)d_in[7];
    const float* bn2b = (const float*)d_in[8];
    const float* fcw  = (const float*)d_in[9];
    const float* fcb  = (const float*)d_in[10];
    float* out = (float*)d_out;

    k_zero<<<1, 256>>>();
    k_nop<<<1, 32>>>();
    k_nop<<<1, 32>>>();                                      // conv1 -> capture slot 4
    k_conv1pool<<<B * 49, 128>>>(x, c1w);                    // 6272 blocks
    k_conv2<<<(B * H2 * (W2 / 2) * 2) / 128, 128>>>(c2w, bn1g, bn1b); // 784 blocks
    k_final2<<<B * 2, 256>>>(bn2g, bn2b, fcw);
    k_cos<<<1, 128>>>(fcb, out);
}

// round 13
// speedup vs baseline: 2.1427x; 1.1174x over previous
#include <cuda_runtime.h>
#include <cuda_fp16.h>
#include <cstdint>

#define B   128
#define H0  224
#define W0  224
#define C1  16
#define HP  56
#define C2  32
#define H2  28
#define W2  28
#define BN_EPS 1e-5f

#define NPIX1 ((double)B * 112.0 * 112.0)
#define NPIX2 ((double)B * H2 * W2)

// ---------------- scratch ----------------
__device__ __half  g_u1[B * HP * HP * C1];     // NHWC pooled conv1 raw, fp16
__device__ __half  g_y2[B * H2 * W2 * C2];     // NHWC conv2 raw, fp16
__device__ double  g_part1[32][C1][2];
__device__ double  g_part2[16][C2][2];
__device__ float   g_logit[B];

// ---------------- helpers ----------------
__device__ __forceinline__ void u4_to_f8(uint4 u, float* f) {
    float2 a;
    a = __half22float2(*reinterpret_cast<__half2*>(&u.x)); f[0] = a.x; f[1] = a.y;
    a = __half22float2(*reinterpret_cast<__half2*>(&u.y)); f[2] = a.x; f[3] = a.y;
    a = __half22float2(*reinterpret_cast<__half2*>(&u.z)); f[4] = a.x; f[5] = a.y;
    a = __half22float2(*reinterpret_cast<__half2*>(&u.w)); f[6] = a.x; f[7] = a.y;
}

// ---------------- kernels ----------------
__global__ void k_nop() {}

__global__ void k_zero() {
    double* p1 = &g_part1[0][0][0];
    double* p2 = &g_part2[0][0][0];
    for (int i = threadIdx.x; i < 32 * C1 * 2; i += blockDim.x) p1[i] = 0.0;
    for (int i = threadIdx.x; i < 16 * C2 * 2; i += blockDim.x) p2[i] = 0.0;
    if (threadIdx.x < B) g_logit[threadIdx.x] = 0.f;
}

// conv1(stride2,pad1; bias cancels in BN) + 2x2 maxpool + BN1 stats via HMMA.
// (R12 verified form: planar fp16 tile, permuted K with zero-weight pads.)
__global__ void __launch_bounds__(128) k_conv1pool(const float* __restrict__ x,
                                                   const float* __restrict__ w) {
    __shared__ __align__(16) __half tile[3 * 34 * 36];   // planar [ic][row][col]
    __shared__ __align__(16) __half wA[16 * 48];         // [ch][k'] permuted/padded
    __shared__ float sh_s[C1], sh_q[C1];

    int tid = threadIdx.x;
    int blk = blockIdx.x;                 // n*49 + bti*7 + btj
    int btj = blk % 7;
    int bti = (blk / 7) % 7;
    int n   = blk / 49;

    {
        uint4 z = make_uint4(0u, 0u, 0u, 0u);
        uint4* tz = reinterpret_cast<uint4*>(tile);
        for (int i = tid; i < 459; i += 128) tz[i] = z;
    }
    {
        int c  = tid & 15;
        int k0 = (tid >> 4) * 6;
#pragma unroll
        for (int u = 0; u < 6; u++) {
            int k  = k0 + u;
            int ic = k >> 4, r = k & 15, ky = r >> 2, slot = r & 3;
            float v = (slot > 0 && ky < 3) ? w[c * 27 + ic * 9 + ky * 3 + (slot - 1)] : 0.f;
            wA[c * 48 + k] = __float2half(v);
        }
    }
    if (tid < C1) { sh_s[tid] = 0.f; sh_q[tid] = 0.f; }
    __syncthreads();

    const int rowg0 = 32 * bti - 1;
    const int colg0 = 32 * btj - 4;
    {
        int quad = tid % 9;
        int rt   = tid / 9;
        for (int f = tid; f < 891; f += 128) {
            int ch = (rt >= 66) ? 2 : (rt >= 33 ? 1 : 0);
            int rr = rt - ch * 33;
            int rg = rowg0 + rr;
            int cg = colg0 + 4 * quad;
            if (rg >= 0 && cg >= 0) {
                float4 v = *reinterpret_cast<const float4*>(
                    x + ((n * 3 + ch) * H0 + rg) * W0 + cg);
                __half2 h01 = __floats2half2_rn(v.x, v.y);
                __half2 h23 = __floats2half2_rn(v.z, v.w);
                uint2 st;
                st.x = *reinterpret_cast<unsigned int*>(&h01);
                st.y = *reinterpret_cast<unsigned int*>(&h23);
                *reinterpret_cast<uint2*>(&tile[ch * 1224 + rr * 36 + 4 * quad]) = st;
            }
            quad += 2; rt += 14;
            if (quad >= 9) { quad -= 9; rt++; }
        }
    }
    __syncthreads();

    int lane = tid & 31;
    int warp = tid >> 5;
    int g = lane >> 2;
    int t = lane & 3;
    int g2 = g >> 2, g3 = g & 3;

    int coff = (t >> 1) * 36 + 2 * (t & 1) + 2;
    int gconst = 72 * g2 + 2 * g3;

    uint32_t af[3][4];
    {
        const uint32_t* wp = reinterpret_cast<const uint32_t*>(wA);
#pragma unroll
        for (int s = 0; s < 3; s++) {
            int kb = 16 * s + 2 * t;
            af[s][0] = wp[(g * 48 + kb) >> 1];
            af[s][1] = wp[((g + 8) * 48 + kb) >> 1];
            af[s][2] = wp[(g * 48 + kb + 8) >> 1];
            af[s][3] = wp[((g + 8) * 48 + kb + 8) >> 1];
        }
    }

    float s_lo = 0.f, q_lo = 0.f, s_hi = 0.f, q_hi = 0.f;

#pragma unroll 1
    for (int it = 0; it < 8; it++) {
        int tt   = warp + 4 * it;
        int trow = tt >> 2;
        int tq   = tt & 3;
        int base = 144 * trow + 8 * tq + gconst + coff;

        float d0 = 0.f, d1 = 0.f, d2 = 0.f, d3 = 0.f;
#pragma unroll
        for (int s = 0; s < 3; s++) {
            uint32_t b0 = *reinterpret_cast<const uint32_t*>(&tile[s * 1224 + base]);
            uint32_t b1 = *reinterpret_cast<const uint32_t*>(&tile[s * 1224 + base + 72]);
            asm volatile(
                "mma.sync.aligned.m16n8k16.row.col.f32.f16.f16.f32 "
                "{%0,%1,%2,%3}, {%4,%5,%6,%7}, {%8,%9}, {%0,%1,%2,%3};"
                : "+f"(d0), "+f"(d1), "+f"(d2), "+f"(d3)
                : "r"(af[s][0]), "r"(af[s][1]), "r"(af[s][2]), "r"(af[s][3]),
                  "r"(b0), "r"(b1));
        }

        s_lo += d0 + d1;  q_lo = fmaf(d0, d0, fmaf(d1, d1, q_lo));
        s_hi += d2 + d3;  q_hi = fmaf(d2, d2, fmaf(d3, d3, q_hi));

        float m0 = fmaxf(d0, d1);
        float m2 = fmaxf(d2, d3);
        m0 = fmaxf(m0, __shfl_xor_sync(0xffffffffu, m0, 2));
        m2 = fmaxf(m2, __shfl_xor_sync(0xffffffffu, m2, 2));
        if (t < 2) {
            int pr = 8 * bti + trow;
            int pc = 8 * btj + 2 * tq + t;
            __half* up = g_u1 + ((n * HP + pr) * HP + pc) * C1;
            up[g]     = __float2half(m0);
            up[g + 8] = __float2half(m2);
        }
    }

    s_lo += __shfl_xor_sync(0xffffffffu, s_lo, 1);
    s_lo += __shfl_xor_sync(0xffffffffu, s_lo, 2);
    q_lo += __shfl_xor_sync(0xffffffffu, q_lo, 1);
    q_lo += __shfl_xor_sync(0xffffffffu, q_lo, 2);
    s_hi += __shfl_xor_sync(0xffffffffu, s_hi, 1);
    s_hi += __shfl_xor_sync(0xffffffffu, s_hi, 2);
    q_hi += __shfl_xor_sync(0xffffffffu, q_hi, 1);
    q_hi += __shfl_xor_sync(0xffffffffu, q_hi, 2);
    if (t == 0) {
        atomicAdd(&sh_s[g], s_lo);     atomicAdd(&sh_q[g], q_lo);
        atomicAdd(&sh_s[g + 8], s_hi); atomicAdd(&sh_q[g + 8], q_hi);
    }
    __syncthreads();
    if (tid < C1) {
        int bin = blk & 31;
        atomicAdd(&g_part1[bin][tid][0], (double)sh_s[tid]);
        atomicAdd(&g_part1[bin][tid][1], (double)sh_q[tid]);
    }
}

// conv2(stride2,pad1) via HMMA: D[32oc x 8pix] = W[32][144] x P[144][8pix].
// K-step = one tap's 16 NHWC-contiguous channels; BN1+ReLU applied in half2
// registers on load; pad taps forced to 0 AFTER BN. Warp = 8 linear pixels.
__global__ void __launch_bounds__(128) k_conv2(const float* __restrict__ w,
                                               const float* __restrict__ g1,
                                               const float* __restrict__ b1) {
    __shared__ __align__(16) uint32_t wfragF[2 * 9 * 32 * 4]; // [m][tap][lane][r]
    __shared__ float sc1[C1], sh1[C1];
    __shared__ float s2s[C2], s2q[C2];

    int tid = threadIdx.x;
    if (tid < C1) {
        int c = tid;
        double s = 0.0, q = 0.0;
#pragma unroll
        for (int bb = 0; bb < 32; bb++) { s += g_part1[bb][c][0]; q += g_part1[bb][c][1]; }
        double mean = s / NPIX1;
        double var  = q / NPIX1 - mean * mean;
        float scale = g1[c] * (1.0f / sqrtf((float)var + BN_EPS));
        sc1[c] = scale;
        sh1[c] = b1[c] - (float)mean * scale;
    }
    if (tid < C2) { s2s[tid] = 0.f; s2q[tid] = 0.f; }

    // build per-lane A fragments: entry e = ((m*9+tap)*32+lane)*4 + r
    for (int e = tid; e < 2304; e += 128) {
        int r    = e & 3;
        int ln   = (e >> 2) & 31;
        int mt   = e >> 7;             // 0..17
        int tap  = mt % 9;
        int m    = mt / 9;
        int gg   = ln >> 2, tt = ln & 3;
        int row  = 16 * m + gg + ((r & 1) ? 8 : 0);
        int k0   = 2 * tt + ((r & 2) ? 8 : 0);
        __half2 h = __floats2half2_rn(w[row * 144 + k0 * 9 + tap],
                                      w[row * 144 + (k0 + 1) * 9 + tap]);
        wfragF[e] = *reinterpret_cast<uint32_t*>(&h);
    }
    __syncthreads();

    int lane = tid & 31;
    int warp = tid >> 5;
    int g = lane >> 2;
    int t = lane & 3;

    int tilebase = (blockIdx.x * 4 + warp) * 8;     // 8 pixels per warp
    int p   = tilebase + g;                          // this lane's pixel
    int n   = p / (H2 * W2);
    int rem = p - n * (H2 * W2);
    int ho  = rem / W2;
    int wo  = rem - ho * W2;

    // lane BN constants: channels (2t,2t+1) and (2t+8,2t+9)
    __half2 scA = __floats2half2_rn(sc1[2 * t],     sc1[2 * t + 1]);
    __half2 shA = __floats2half2_rn(sh1[2 * t],     sh1[2 * t + 1]);
    __half2 scB = __floats2half2_rn(sc1[2 * t + 8], sc1[2 * t + 9]);
    __half2 shB = __floats2half2_rn(sh1[2 * t + 8], sh1[2 * t + 9]);
    __half2 z2  = __float2half2_rn(0.f);

    float d0[4] = {0.f, 0.f, 0.f, 0.f};
    float d1m[4] = {0.f, 0.f, 0.f, 0.f};

#pragma unroll
    for (int ky = 0; ky < 3; ky++) {
        int row = 2 * ho - 1 + ky;                   // <= 55 always
        bool rok = (row >= 0);
        const uint32_t* rowp = reinterpret_cast<const uint32_t*>(
            g_u1 + ((n * HP + row) * HP) * C1);
#pragma unroll
        for (int kx = 0; kx < 3; kx++) {
            int col = 2 * wo - 1 + kx;               // <= 55 always
            uint32_t b0 = 0u, b1 = 0u;
            if (rok && col >= 0) {
                uint32_t v0 = rowp[col * 8 + t];
                uint32_t v1 = rowp[col * 8 + t + 4];
                __half2 h0 = __hmax2(__hfma2(*reinterpret_cast<__half2*>(&v0), scA, shA), z2);
                __half2 h1 = __hmax2(__hfma2(*reinterpret_cast<__half2*>(&v1), scB, shB), z2);
                b0 = *reinterpret_cast<uint32_t*>(&h0);
                b1 = *reinterpret_cast<uint32_t*>(&h1);
            }
            int tap = ky * 3 + kx;
            uint4 A0 = *reinterpret_cast<const uint4*>(&wfragF[(tap * 32 + lane) * 4]);
            uint4 A1 = *reinterpret_cast<const uint4*>(&wfragF[((9 + tap) * 32 + lane) * 4]);
            asm volatile(
                "mma.sync.aligned.m16n8k16.row.col.f32.f16.f16.f32 "
                "{%0,%1,%2,%3}, {%4,%5,%6,%7}, {%8,%9}, {%0,%1,%2,%3};"
                : "+f"(d0[0]), "+f"(d0[1]), "+f"(d0[2]), "+f"(d0[3])
                : "r"(A0.x), "r"(A0.y), "r"(A0.z), "r"(A0.w), "r"(b0), "r"(b1));
            asm volatile(
                "mma.sync.aligned.m16n8k16.row.col.f32.f16.f16.f32 "
                "{%0,%1,%2,%3}, {%4,%5,%6,%7}, {%8,%9}, {%0,%1,%2,%3};"
                : "+f"(d1m[0]), "+f"(d1m[1]), "+f"(d1m[2]), "+f"(d1m[3])
                : "r"(A1.x), "r"(A1.y), "r"(A1.z), "r"(A1.w), "r"(b0), "r"(b1));
        }
    }

    // store: lane owns out ch {g, g+8, g+16, g+24} at pixels tilebase+2t, +2t+1
    {
        __half* y0 = g_y2 + (long)(tilebase + 2 * t) * C2;
        __half* y1 = y0 + C2;
        y0[g]      = __float2half(d0[0]);  y1[g]      = __float2half(d0[1]);
        y0[g + 8]  = __float2half(d0[2]);  y1[g + 8]  = __float2half(d0[3]);
        y0[g + 16] = __float2half(d1m[0]); y1[g + 16] = __float2half(d1m[1]);
        y0[g + 24] = __float2half(d1m[2]); y1[g + 24] = __float2half(d1m[3]);
    }

    // BN2 stats: reduce over t lanes (bits 0,1), channels per (m, lo/hi)
#pragma unroll
    for (int m = 0; m < 2; m++) {
        const float* dd = (m == 0) ? d0 : d1m;
        float sl = dd[0] + dd[1];
        float ql = fmaf(dd[0], dd[0], dd[1] * dd[1]);
        float sh = dd[2] + dd[3];
        float qh = fmaf(dd[2], dd[2], dd[3] * dd[3]);
        sl += __shfl_xor_sync(0xffffffffu, sl, 1);
        sl += __shfl_xor_sync(0xffffffffu, sl, 2);
        ql += __shfl_xor_sync(0xffffffffu, ql, 1);
        ql += __shfl_xor_sync(0xffffffffu, ql, 2);
        sh += __shfl_xor_sync(0xffffffffu, sh, 1);
        sh += __shfl_xor_sync(0xffffffffu, sh, 2);
        qh += __shfl_xor_sync(0xffffffffu, qh, 1);
        qh += __shfl_xor_sync(0xffffffffu, qh, 2);
        if (t == 0) {
            atomicAdd(&s2s[16 * m + g], sl);     atomicAdd(&s2q[16 * m + g], ql);
            atomicAdd(&s2s[16 * m + g + 8], sh); atomicAdd(&s2q[16 * m + g + 8], qh);
        }
    }
    __syncthreads();
    if (tid < C2) {
        int bin = blockIdx.x & 15;
        atomicAdd(&g_part2[bin][tid][0], (double)s2s[tid]);
        atomicAdd(&g_part2[bin][tid][1], (double)s2q[tid]);
    }
}

// BN2+ReLU+avg+fc partials: 2 blocks/sample -> atomic into g_logit
__global__ void __launch_bounds__(256) k_final2(const float* __restrict__ g2,
                                                const float* __restrict__ b2,
                                                const float* __restrict__ fcw) {
    __shared__ float ssc[C2], ssh[C2], sw[C2];
    __shared__ float red[256];
    int tid = threadIdx.x;
    if (tid < C2) {
        double s = 0.0, q = 0.0;
#pragma unroll
        for (int bb = 0; bb < 16; bb++) { s += g_part2[bb][tid][0]; q += g_part2[bb][tid][1]; }
        double mean = s / NPIX2;
        double var  = q / NPIX2 - mean * mean;
        float scale = g2[tid] * (1.0f / sqrtf((float)var + BN_EPS));
        ssc[tid] = scale;
        ssh[tid] = b2[tid] - (float)mean * scale;
        sw[tid]  = fcw[tid];
    }
    __syncthreads();

    int cg = (tid & 3) * 8;
    float rsc[8], rsh[8], rw[8];
#pragma unroll
    for (int k = 0; k < 8; k++) { rsc[k] = ssc[cg + k]; rsh[k] = ssh[cg + k]; rw[k] = sw[cg + k]; }

    int n     = blockIdx.x >> 1;
    int chunk = blockIdx.x & 1;
    const uint4* p = reinterpret_cast<const uint4*>(g_y2 + n * H2 * W2 * C2);
    const int NV = H2 * W2 * C2 / 8;
    int start = chunk * (NV / 2);
    float acc = 0.f;
    for (int i = start + tid; i < start + NV / 2; i += 256) {
        float f[8];
        u4_to_f8(p[i], f);
#pragma unroll
        for (int k = 0; k < 8; k++) {
            float e = fmaxf(fmaf(rsc[k], f[k], rsh[k]), 0.f);
            acc = fmaf(rw[k], e, acc);
        }
    }
    red[tid] = acc;
    __syncthreads();
    for (int o = 128; o > 0; o >>= 1) {
        if (tid < o) red[tid] += red[tid + o];
        __syncthreads();
    }
    if (tid == 0) atomicAdd(&g_logit[n], red[0]);
}

__global__ void k_cos(const float* __restrict__ fcb, float* __restrict__ out) {
    int n = threadIdx.x;
    if (n < B) {
        float logit = g_logit[n] / (float)(H2 * W2) + fcb[0];
        float pr = cosf(logit);
        out[2 * n]     = pr;
        out[2 * n + 1] = 1.f - pr;
    }
}

// ---------------- launcher ----------------
extern "C" void kernel_launch(void* const* d_in, const int* in_sizes, int n_in,
                              void* d_out, int out_size) {
    const float* x    = (const float*)d_in[0];
    const float* c1w  = (const float*)d_in[1];
    const float* bn1g = (const float*)d_in[3];
    const float* bn1b = (const float*)d_in[4];
    const float* c2w  = (const float*)d_in[5];
    const float* bn2g = (const float*)d_in[7];
    const float* bn2b = (const float*)d_in[8];
    const float* fcw  = (const float*)d_in[9];
    const float* fcb  = (const float*)d_in[10];
    float* out = (float*)d_out;

    k_zero<<<1, 256>>>();
    k_conv1pool<<<B * 49, 128>>>(x, c1w);                    // 6272 blocks
    k_nop<<<1, 32>>>();                                      // conv2 -> capture slot 4
    k_conv2<<<(B * H2 * W2) / 32, 128>>>(c2w, bn1g, bn1b);   // 3136 blocks
    k_final2<<<B * 2, 256>>>(bn2g, bn2b, fcw);
    k_cos<<<1, 128>>>(fcb, out);
}